// round 1
// baseline (speedup 1.0000x reference)
#include <cuda_runtime.h>

#define W 4096
#define S 4096
#define NK 1024
#define SHARP 10.0f

// ---- scratch (device globals; no allocations allowed) ----
__device__ __align__(16) float g_mix_re[W];
__device__ __align__(16) float g_mix_im[W];
__device__ float g_corr[NK];
__device__ float g_att[NK];
__device__ __align__(16) float g_ck_re[W];
__device__ __align__(16) float g_ck_im[W];
__device__ float g_pr[32 * W];
__device__ float g_pi[32 * W];

// ---------------------------------------------------------------------------
// Stage 1: noisy_mix[w] = sum_s holo[w,s] * conj(cue[w,s])
//   re = hr*cr + hi*ci ; im = hi*cr - hr*ci
// One block per row w, float4 vectorized, 2-level reduction.
// ---------------------------------------------------------------------------
__global__ void k_mix(const float4* __restrict__ hr, const float4* __restrict__ hi,
                      const float4* __restrict__ cr, const float4* __restrict__ ci) {
    const int w = blockIdx.x;
    const size_t base = (size_t)w * (S / 4);
    float are = 0.f, aim = 0.f;
    for (int i = threadIdx.x; i < S / 4; i += blockDim.x) {
        float4 a = hr[base + i];
        float4 b = hi[base + i];
        float4 c = cr[base + i];
        float4 d = ci[base + i];
        are += a.x * c.x + b.x * d.x;  aim += b.x * c.x - a.x * d.x;
        are += a.y * c.y + b.y * d.y;  aim += b.y * c.y - a.y * d.y;
        are += a.z * c.z + b.z * d.z;  aim += b.z * c.z - a.z * d.z;
        are += a.w * c.w + b.w * d.w;  aim += b.w * c.w - a.w * d.w;
    }
    __shared__ float s1[32], s2[32];
    #pragma unroll
    for (int o = 16; o > 0; o >>= 1) {
        are += __shfl_down_sync(0xffffffffu, are, o);
        aim += __shfl_down_sync(0xffffffffu, aim, o);
    }
    const int lane = threadIdx.x & 31, wid = threadIdx.x >> 5;
    if (lane == 0) { s1[wid] = are; s2[wid] = aim; }
    __syncthreads();
    if (wid == 0) {
        const int nw = blockDim.x >> 5;
        are = (lane < nw) ? s1[lane] : 0.f;
        aim = (lane < nw) ? s2[lane] : 0.f;
        #pragma unroll
        for (int o = 16; o > 0; o >>= 1) {
            are += __shfl_down_sync(0xffffffffu, are, o);
            aim += __shfl_down_sync(0xffffffffu, aim, o);
        }
        if (lane == 0) { g_mix_re[w] = are; g_mix_im[w] = aim; }
    }
}

// ---------------------------------------------------------------------------
// Stage 2: corr[n] = | keys[n,:] . mix |   (plain complex dot, NO conjugate)
//   re = kr*mr - ki*mi ; im = kr*mi + ki*mr
// One block per key n. mix (32KB) stays L2/L1-resident across all 1024 blocks.
// ---------------------------------------------------------------------------
__global__ void k_corr(const float4* __restrict__ kr, const float4* __restrict__ ki) {
    const int n = blockIdx.x;
    const size_t base = (size_t)n * (W / 4);
    const float4* __restrict__ mr = (const float4*)g_mix_re;
    const float4* __restrict__ mi = (const float4*)g_mix_im;
    float ar = 0.f, ai = 0.f;
    for (int i = threadIdx.x; i < W / 4; i += blockDim.x) {
        float4 a = kr[base + i];
        float4 b = ki[base + i];
        float4 c = mr[i];
        float4 d = mi[i];
        ar += a.x * c.x - b.x * d.x;  ai += a.x * d.x + b.x * c.x;
        ar += a.y * c.y - b.y * d.y;  ai += a.y * d.y + b.y * c.y;
        ar += a.z * c.z - b.z * d.z;  ai += a.z * d.z + b.z * c.z;
        ar += a.w * c.w - b.w * d.w;  ai += a.w * d.w + b.w * c.w;
    }
    __shared__ float s1[32], s2[32];
    #pragma unroll
    for (int o = 16; o > 0; o >>= 1) {
        ar += __shfl_down_sync(0xffffffffu, ar, o);
        ai += __shfl_down_sync(0xffffffffu, ai, o);
    }
    const int lane = threadIdx.x & 31, wid = threadIdx.x >> 5;
    if (lane == 0) { s1[wid] = ar; s2[wid] = ai; }
    __syncthreads();
    if (wid == 0) {
        const int nw = blockDim.x >> 5;
        ar = (lane < nw) ? s1[lane] : 0.f;
        ai = (lane < nw) ? s2[lane] : 0.f;
        #pragma unroll
        for (int o = 16; o > 0; o >>= 1) {
            ar += __shfl_down_sync(0xffffffffu, ar, o);
            ai += __shfl_down_sync(0xffffffffu, ai, o);
        }
        if (lane == 0) g_corr[n] = sqrtf(ar * ar + ai * ai);
    }
}

// ---------------------------------------------------------------------------
// Stage 3: attention = softmax(corr * SHARP). Single block of NK threads.
// ---------------------------------------------------------------------------
__global__ void k_softmax() {
    __shared__ float sm[NK];
    const int t = threadIdx.x;
    const float x = g_corr[t] * SHARP;
    sm[t] = x;
    __syncthreads();
    #pragma unroll
    for (int o = NK / 2; o > 0; o >>= 1) {
        if (t < o) sm[t] = fmaxf(sm[t], sm[t + o]);
        __syncthreads();
    }
    const float mx = sm[0];
    __syncthreads();
    const float e = expf(x - mx);
    sm[t] = e;
    __syncthreads();
    #pragma unroll
    for (int o = NK / 2; o > 0; o >>= 1) {
        if (t < o) sm[t] += sm[t + o];
        __syncthreads();
    }
    g_att[t] = e / sm[0];
}

// ---------------------------------------------------------------------------
// Stage 4a: partial clean_key: for key-chunk c (32 keys), column-parallel
//   p[c,w] = sum_{n in chunk} att[n] * keys[n,w]
// grid = (W/256, 32). Coalesced across w; fully unrolled for MLP.
// ---------------------------------------------------------------------------
__global__ void k_clean(const float* __restrict__ kr, const float* __restrict__ ki) {
    const int w = blockIdx.x * blockDim.x + threadIdx.x;
    const int c = blockIdx.y;
    const int n0 = c * 32;
    float re = 0.f, im = 0.f;
    #pragma unroll
    for (int j = 0; j < 32; j++) {
        const int n = n0 + j;
        const float a = g_att[n];
        const size_t off = (size_t)n * W + w;
        re = fmaf(a, __ldg(kr + off), re);
        im = fmaf(a, __ldg(ki + off), im);
    }
    g_pr[c * W + w] = re;
    g_pi[c * W + w] = im;
}

// Stage 4b: fold the 32 partials (deterministic, no atomics).
__global__ void k_clean2() {
    const int w = blockIdx.x * blockDim.x + threadIdx.x;
    float re = 0.f, im = 0.f;
    #pragma unroll
    for (int c = 0; c < 32; c++) {
        re += g_pr[c * W + w];
        im += g_pi[c * W + w];
    }
    g_ck_re[w] = re;
    g_ck_im[w] = im;
}

// ---------------------------------------------------------------------------
// Stage 5: out[0] = hr*ckr - hi*cki ; out[1] = hr*cki + hi*ckr
// float4 streaming; clean_key broadcast per row (uniform within warp).
// ---------------------------------------------------------------------------
__global__ void k_out(const float4* __restrict__ hr, const float4* __restrict__ hi,
                      float4* __restrict__ out) {
    const size_t i = (size_t)blockIdx.x * blockDim.x + threadIdx.x;
    const int w = (int)(i >> 10);  // S/4 = 1024 float4 per row
    const float ckr = g_ck_re[w];
    const float cki = g_ck_im[w];
    const float4 a = hr[i];
    const float4 b = hi[i];
    float4 o0, o1;
    o0.x = a.x * ckr - b.x * cki;  o1.x = fmaf(a.x, cki, b.x * ckr);
    o0.y = a.y * ckr - b.y * cki;  o1.y = fmaf(a.y, cki, b.y * ckr);
    o0.z = a.z * ckr - b.z * cki;  o1.z = fmaf(a.z, cki, b.z * ckr);
    o0.w = a.w * ckr - b.w * cki;  o1.w = fmaf(a.w, cki, b.w * ckr);
    out[i] = o0;
    out[i + (size_t)W * (S / 4)] = o1;
}

extern "C" void kernel_launch(void* const* d_in, const int* in_sizes, int n_in,
                              void* d_out, int out_size) {
    const float* holo_re = (const float*)d_in[0];
    const float* holo_im = (const float*)d_in[1];
    const float* cue_re  = (const float*)d_in[2];
    const float* cue_im  = (const float*)d_in[3];
    const float* keys_re = (const float*)d_in[4];
    const float* keys_im = (const float*)d_in[5];
    float* out = (float*)d_out;

    k_mix<<<W, 256>>>((const float4*)holo_re, (const float4*)holo_im,
                      (const float4*)cue_re, (const float4*)cue_im);
    k_corr<<<NK, 256>>>((const float4*)keys_re, (const float4*)keys_im);
    k_softmax<<<1, NK>>>();
    {
        dim3 grid(W / 256, 32);
        k_clean<<<grid, 256>>>(keys_re, keys_im);
    }
    k_clean2<<<W / 256, 256>>>();
    k_out<<<(W * (S / 4)) / 256, 256>>>((const float4*)holo_re, (const float4*)holo_im,
                                        (float4*)out);
}

// round 2
// speedup vs baseline: 1.0173x; 1.0173x over previous
#include <cuda_runtime.h>

#define W 4096
#define S 4096
#define NK 1024
#define SHARP 10.0f
#define NCHUNK 64          // key chunks for stage 4
#define KPC (NK / NCHUNK)  // 16 keys per chunk

// ---- scratch (device globals; no allocations allowed) ----
__device__ __align__(16) float g_mix_re[W];
__device__ __align__(16) float g_mix_im[W];
__device__ float g_corr[NK];
__device__ __align__(16) float g_att[NK];
__device__ __align__(16) float g_ck_re[W];
__device__ __align__(16) float g_ck_im[W];
__device__ __align__(16) float g_pr[NCHUNK * W];
__device__ __align__(16) float g_pi[NCHUNK * W];

// ---------------------------------------------------------------------------
// Stage 1: noisy_mix[w] = sum_s holo[w,s] * conj(cue[w,s])
//   re = hr*cr + hi*ci ; im = hi*cr - hr*ci
// One block (256 thr) per row; fixed 16-iteration loop, unroll 4 for MLP.
// All four streams are 128MB (no L2 reuse possible) -> __ldcs.
// ---------------------------------------------------------------------------
__global__ void __launch_bounds__(256) k_mix(
        const float4* __restrict__ hr, const float4* __restrict__ hi,
        const float4* __restrict__ cr, const float4* __restrict__ ci) {
    const int w = blockIdx.x;
    const size_t base = (size_t)w * (S / 4) + threadIdx.x;
    float are = 0.f, aim = 0.f;
    #pragma unroll 4
    for (int it = 0; it < (S / 4) / 256; it++) {
        const size_t idx = base + (size_t)it * 256;
        float4 a = __ldcs(hr + idx);
        float4 b = __ldcs(hi + idx);
        float4 c = __ldcs(cr + idx);
        float4 d = __ldcs(ci + idx);
        are += a.x * c.x + b.x * d.x;  aim += b.x * c.x - a.x * d.x;
        are += a.y * c.y + b.y * d.y;  aim += b.y * c.y - a.y * d.y;
        are += a.z * c.z + b.z * d.z;  aim += b.z * c.z - a.z * d.z;
        are += a.w * c.w + b.w * d.w;  aim += b.w * c.w - a.w * d.w;
    }
    __shared__ float s1[8], s2[8];
    #pragma unroll
    for (int o = 16; o > 0; o >>= 1) {
        are += __shfl_down_sync(0xffffffffu, are, o);
        aim += __shfl_down_sync(0xffffffffu, aim, o);
    }
    const int lane = threadIdx.x & 31, wid = threadIdx.x >> 5;
    if (lane == 0) { s1[wid] = are; s2[wid] = aim; }
    __syncthreads();
    if (wid == 0) {
        are = (lane < 8) ? s1[lane] : 0.f;
        aim = (lane < 8) ? s2[lane] : 0.f;
        #pragma unroll
        for (int o = 4; o > 0; o >>= 1) {
            are += __shfl_down_sync(0xffffffffu, are, o);
            aim += __shfl_down_sync(0xffffffffu, aim, o);
        }
        if (lane == 0) { g_mix_re[w] = are; g_mix_im[w] = aim; }
    }
}

// ---------------------------------------------------------------------------
// Stage 2: corr[n] = | keys[n,:] . mix |   (plain complex dot, NO conjugate)
// One block per key. Default caching for keys: they're re-read by k_clean,
// and 32MB fits L2.
// ---------------------------------------------------------------------------
__global__ void __launch_bounds__(256) k_corr(
        const float4* __restrict__ kr, const float4* __restrict__ ki) {
    const int n = blockIdx.x;
    const size_t base = (size_t)n * (W / 4) + threadIdx.x;
    const float4* __restrict__ mr = (const float4*)g_mix_re;
    const float4* __restrict__ mi = (const float4*)g_mix_im;
    float ar = 0.f, ai = 0.f;
    #pragma unroll 4
    for (int it = 0; it < (W / 4) / 256; it++) {
        const int i = threadIdx.x + it * 256;
        float4 a = kr[base + (size_t)it * 256];
        float4 b = ki[base + (size_t)it * 256];
        float4 c = mr[i];
        float4 d = mi[i];
        ar += a.x * c.x - b.x * d.x;  ai += a.x * d.x + b.x * c.x;
        ar += a.y * c.y - b.y * d.y;  ai += a.y * d.y + b.y * c.y;
        ar += a.z * c.z - b.z * d.z;  ai += a.z * d.z + b.z * c.z;
        ar += a.w * c.w - b.w * d.w;  ai += a.w * d.w + b.w * c.w;
    }
    __shared__ float s1[8], s2[8];
    #pragma unroll
    for (int o = 16; o > 0; o >>= 1) {
        ar += __shfl_down_sync(0xffffffffu, ar, o);
        ai += __shfl_down_sync(0xffffffffu, ai, o);
    }
    const int lane = threadIdx.x & 31, wid = threadIdx.x >> 5;
    if (lane == 0) { s1[wid] = ar; s2[wid] = ai; }
    __syncthreads();
    if (wid == 0) {
        ar = (lane < 8) ? s1[lane] : 0.f;
        ai = (lane < 8) ? s2[lane] : 0.f;
        #pragma unroll
        for (int o = 4; o > 0; o >>= 1) {
            ar += __shfl_down_sync(0xffffffffu, ar, o);
            ai += __shfl_down_sync(0xffffffffu, ai, o);
        }
        if (lane == 0) g_corr[n] = sqrtf(ar * ar + ai * ai);
    }
}

// ---------------------------------------------------------------------------
// Stage 3: attention = softmax(corr * SHARP). Single block of NK threads.
// ---------------------------------------------------------------------------
__global__ void k_softmax() {
    __shared__ float sm[NK];
    const int t = threadIdx.x;
    const float x = g_corr[t] * SHARP;
    sm[t] = x;
    __syncthreads();
    #pragma unroll
    for (int o = NK / 2; o > 0; o >>= 1) {
        if (t < o) sm[t] = fmaxf(sm[t], sm[t + o]);
        __syncthreads();
    }
    const float mx = sm[0];
    __syncthreads();
    const float e = expf(x - mx);
    sm[t] = e;
    __syncthreads();
    #pragma unroll
    for (int o = NK / 2; o > 0; o >>= 1) {
        if (t < o) sm[t] += sm[t + o];
        __syncthreads();
    }
    g_att[t] = e / sm[0];
}

// ---------------------------------------------------------------------------
// Stage 4a: per key-chunk partials of clean_key, float4-vectorized.
//   p[c, w] = sum_{n in chunk c} att[n] * keys[n, w]
// grid = (8, NCHUNK), block = 128. Keys should hit L2 (loaded by k_corr).
// ---------------------------------------------------------------------------
__global__ void __launch_bounds__(128) k_clean(
        const float4* __restrict__ kr, const float4* __restrict__ ki) {
    const int w4 = blockIdx.x * 128 + threadIdx.x;  // 0 .. W/4-1
    const int c = blockIdx.y;
    const int n0 = c * KPC;
    float4 re = make_float4(0.f, 0.f, 0.f, 0.f);
    float4 im = make_float4(0.f, 0.f, 0.f, 0.f);
    #pragma unroll 8
    for (int j = 0; j < KPC; j++) {
        const int n = n0 + j;
        const float a = g_att[n];
        const size_t off = (size_t)n * (W / 4) + w4;
        float4 x = kr[off];
        float4 y = ki[off];
        re.x = fmaf(a, x.x, re.x);  im.x = fmaf(a, y.x, im.x);
        re.y = fmaf(a, x.y, re.y);  im.y = fmaf(a, y.y, im.y);
        re.z = fmaf(a, x.z, re.z);  im.z = fmaf(a, y.z, im.z);
        re.w = fmaf(a, x.w, re.w);  im.w = fmaf(a, y.w, im.w);
    }
    ((float4*)g_pr)[(size_t)c * (W / 4) + w4] = re;
    ((float4*)g_pi)[(size_t)c * (W / 4) + w4] = im;
}

// Stage 4b: fold the NCHUNK partials (deterministic, float4).
__global__ void __launch_bounds__(256) k_clean2() {
    const int w4 = blockIdx.x * 256 + threadIdx.x;  // 0 .. W/4-1
    const float4* __restrict__ pr = (const float4*)g_pr;
    const float4* __restrict__ pi = (const float4*)g_pi;
    float4 re = make_float4(0.f, 0.f, 0.f, 0.f);
    float4 im = make_float4(0.f, 0.f, 0.f, 0.f);
    #pragma unroll 8
    for (int c = 0; c < NCHUNK; c++) {
        float4 x = pr[(size_t)c * (W / 4) + w4];
        float4 y = pi[(size_t)c * (W / 4) + w4];
        re.x += x.x;  re.y += x.y;  re.z += x.z;  re.w += x.w;
        im.x += y.x;  im.y += y.y;  im.z += y.z;  im.w += y.w;
    }
    ((float4*)g_ck_re)[w4] = re;
    ((float4*)g_ck_im)[w4] = im;
}

// ---------------------------------------------------------------------------
// Stage 5: out[0] = hr*ckr - hi*cki ; out[1] = hr*cki + hi*ckr
// Pure streaming: __ldcs reads, __stcs writes.
// ---------------------------------------------------------------------------
__global__ void __launch_bounds__(256) k_out(
        const float4* __restrict__ hr, const float4* __restrict__ hi,
        float4* __restrict__ out) {
    const size_t i = (size_t)blockIdx.x * 256 + threadIdx.x;
    const int w = (int)(i >> 10);  // S/4 = 1024 float4 per row
    const float ckr = g_ck_re[w];
    const float cki = g_ck_im[w];
    const float4 a = __ldcs(hr + i);
    const float4 b = __ldcs(hi + i);
    float4 o0, o1;
    o0.x = a.x * ckr - b.x * cki;  o1.x = fmaf(a.x, cki, b.x * ckr);
    o0.y = a.y * ckr - b.y * cki;  o1.y = fmaf(a.y, cki, b.y * ckr);
    o0.z = a.z * ckr - b.z * cki;  o1.z = fmaf(a.z, cki, b.z * ckr);
    o0.w = a.w * ckr - b.w * cki;  o1.w = fmaf(a.w, cki, b.w * ckr);
    __stcs(out + i, o0);
    __stcs(out + i + (size_t)W * (S / 4), o1);
}

extern "C" void kernel_launch(void* const* d_in, const int* in_sizes, int n_in,
                              void* d_out, int out_size) {
    const float* holo_re = (const float*)d_in[0];
    const float* holo_im = (const float*)d_in[1];
    const float* cue_re  = (const float*)d_in[2];
    const float* cue_im  = (const float*)d_in[3];
    const float* keys_re = (const float*)d_in[4];
    const float* keys_im = (const float*)d_in[5];
    float* out = (float*)d_out;

    k_mix<<<W, 256>>>((const float4*)holo_re, (const float4*)holo_im,
                      (const float4*)cue_re, (const float4*)cue_im);
    k_corr<<<NK, 256>>>((const float4*)keys_re, (const float4*)keys_im);
    k_softmax<<<1, NK>>>();
    {
        dim3 grid((W / 4) / 128, NCHUNK);
        k_clean<<<grid, 128>>>((const float4*)keys_re, (const float4*)keys_im);
    }
    k_clean2<<<(W / 4) / 256, 256>>>();
    k_out<<<(W * (S / 4)) / 256, 256>>>((const float4*)holo_re, (const float4*)holo_im,
                                        (float4*)out);
}

// round 3
// speedup vs baseline: 1.0937x; 1.0751x over previous
#include <cuda_runtime.h>

#define W 4096
#define S 4096
#define NK 1024
#define SHARP 10.0f
#define ATT_EPS 1e-8f   // keys below this attention contribute <1e-5 rel -> drop

// ---- scratch (device globals; no allocations allowed) ----
__device__ __align__(16) float g_mix_re[W];
__device__ __align__(16) float g_mix_im[W];
__device__ float g_corr[NK];
__device__ int   g_cidx[NK];   // compacted key indices with att > ATT_EPS
__device__ float g_catt[NK];   // their attention weights
__device__ int   g_cnt;        // number of compacted entries

// ---------------------------------------------------------------------------
// Stage 1: noisy_mix[w] = sum_s holo[w,s] * conj(cue[w,s])
//   re = hr*cr + hi*ci ; im = hi*cr - hr*ci
// One block (256 thr) per row; 16 fixed iterations, streaming loads.
// ---------------------------------------------------------------------------
__global__ void __launch_bounds__(256) k_mix(
        const float4* __restrict__ hr, const float4* __restrict__ hi,
        const float4* __restrict__ cr, const float4* __restrict__ ci) {
    const int w = blockIdx.x;
    const size_t base = (size_t)w * (S / 4) + threadIdx.x;
    float are = 0.f, aim = 0.f;
    #pragma unroll 4
    for (int it = 0; it < (S / 4) / 256; it++) {
        const size_t idx = base + (size_t)it * 256;
        float4 a = __ldcs(hr + idx);
        float4 b = __ldcs(hi + idx);
        float4 c = __ldcs(cr + idx);
        float4 d = __ldcs(ci + idx);
        are += a.x * c.x + b.x * d.x;  aim += b.x * c.x - a.x * d.x;
        are += a.y * c.y + b.y * d.y;  aim += b.y * c.y - a.y * d.y;
        are += a.z * c.z + b.z * d.z;  aim += b.z * c.z - a.z * d.z;
        are += a.w * c.w + b.w * d.w;  aim += b.w * c.w - a.w * d.w;
    }
    __shared__ float s1[8], s2[8];
    #pragma unroll
    for (int o = 16; o > 0; o >>= 1) {
        are += __shfl_down_sync(0xffffffffu, are, o);
        aim += __shfl_down_sync(0xffffffffu, aim, o);
    }
    const int lane = threadIdx.x & 31, wid = threadIdx.x >> 5;
    if (lane == 0) { s1[wid] = are; s2[wid] = aim; }
    __syncthreads();
    if (wid == 0) {
        are = (lane < 8) ? s1[lane] : 0.f;
        aim = (lane < 8) ? s2[lane] : 0.f;
        #pragma unroll
        for (int o = 4; o > 0; o >>= 1) {
            are += __shfl_down_sync(0xffffffffu, are, o);
            aim += __shfl_down_sync(0xffffffffu, aim, o);
        }
        if (lane == 0) { g_mix_re[w] = are; g_mix_im[w] = aim; }
    }
}

// ---------------------------------------------------------------------------
// Stage 2: corr[n] = | keys[n,:] . mix |   (plain complex dot, NO conjugate)
// One block per key; mix (32KB) is L2/L1-resident across blocks.
// ---------------------------------------------------------------------------
__global__ void __launch_bounds__(256) k_corr(
        const float4* __restrict__ kr, const float4* __restrict__ ki) {
    const int n = blockIdx.x;
    const size_t base = (size_t)n * (W / 4) + threadIdx.x;
    const float4* __restrict__ mr = (const float4*)g_mix_re;
    const float4* __restrict__ mi = (const float4*)g_mix_im;
    float ar = 0.f, ai = 0.f;
    #pragma unroll 4
    for (int it = 0; it < (W / 4) / 256; it++) {
        const int i = threadIdx.x + it * 256;
        float4 a = __ldcs(kr + base + (size_t)it * 256);
        float4 b = __ldcs(ki + base + (size_t)it * 256);
        float4 c = mr[i];
        float4 d = mi[i];
        ar += a.x * c.x - b.x * d.x;  ai += a.x * d.x + b.x * c.x;
        ar += a.y * c.y - b.y * d.y;  ai += a.y * d.y + b.y * c.y;
        ar += a.z * c.z - b.z * d.z;  ai += a.z * d.z + b.z * c.z;
        ar += a.w * c.w - b.w * d.w;  ai += a.w * d.w + b.w * c.w;
    }
    __shared__ float s1[8], s2[8];
    #pragma unroll
    for (int o = 16; o > 0; o >>= 1) {
        ar += __shfl_down_sync(0xffffffffu, ar, o);
        ai += __shfl_down_sync(0xffffffffu, ai, o);
    }
    const int lane = threadIdx.x & 31, wid = threadIdx.x >> 5;
    if (lane == 0) { s1[wid] = ar; s2[wid] = ai; }
    __syncthreads();
    if (wid == 0) {
        ar = (lane < 8) ? s1[lane] : 0.f;
        ai = (lane < 8) ? s2[lane] : 0.f;
        #pragma unroll
        for (int o = 4; o > 0; o >>= 1) {
            ar += __shfl_down_sync(0xffffffffu, ar, o);
            ai += __shfl_down_sync(0xffffffffu, ai, o);
        }
        if (lane == 0) g_corr[n] = sqrtf(ar * ar + ai * ai);
    }
}

// ---------------------------------------------------------------------------
// Stage 3: softmax(corr*SHARP) + deterministic compaction of significant keys.
// Single block of NK threads. Prefix-sum (Hillis-Steele) keeps compaction
// order deterministic (index order), so downstream summation order is fixed.
// ---------------------------------------------------------------------------
__global__ void k_soft_compact() {
    __shared__ float sm[NK];
    __shared__ int   sp[NK];
    const int t = threadIdx.x;
    const float x = g_corr[t] * SHARP;
    sm[t] = x;
    __syncthreads();
    #pragma unroll
    for (int o = NK / 2; o > 0; o >>= 1) {
        if (t < o) sm[t] = fmaxf(sm[t], sm[t + o]);
        __syncthreads();
    }
    const float mx = sm[0];
    __syncthreads();
    const float e = expf(x - mx);
    sm[t] = e;
    __syncthreads();
    #pragma unroll
    for (int o = NK / 2; o > 0; o >>= 1) {
        if (t < o) sm[t] += sm[t + o];
        __syncthreads();
    }
    const float att = e / sm[0];
    __syncthreads();
    // inclusive prefix sum of significance flags
    const int flag = (att > ATT_EPS) ? 1 : 0;
    sp[t] = flag;
    __syncthreads();
    #pragma unroll
    for (int o = 1; o < NK; o <<= 1) {
        int v = (t >= o) ? sp[t - o] : 0;
        __syncthreads();
        sp[t] += v;
        __syncthreads();
    }
    if (flag) {
        const int pos = sp[t] - 1;
        g_cidx[pos] = t;
        g_catt[pos] = att;
    }
    if (t == NK - 1) g_cnt = sp[t];
}

// ---------------------------------------------------------------------------
// Stage 4+5 fused: per row w, clean_key[w] = sum_j catt[j]*keys[cidx[j], w]
// (tiny compact list, typically 1 entry), then stream:
//   out[0] = hr*ckr - hi*cki ; out[1] = hr*cki + hi*ckr
// One block per row, 256 threads, 4 float4 iterations.
// ---------------------------------------------------------------------------
__global__ void __launch_bounds__(256) k_out(
        const float4* __restrict__ hr, const float4* __restrict__ hi,
        const float* __restrict__ kr, const float* __restrict__ ki,
        float4* __restrict__ out) {
    const int w = blockIdx.x;
    // every thread computes ck redundantly (cnt ~ 1; loads are L1 broadcast)
    const int cnt = g_cnt;
    float ckr = 0.f, cki = 0.f;
    for (int j = 0; j < cnt; j++) {
        const float a = g_catt[j];
        const size_t off = (size_t)g_cidx[j] * W + w;
        ckr = fmaf(a, __ldg(kr + off), ckr);
        cki = fmaf(a, __ldg(ki + off), cki);
    }
    const size_t base = (size_t)w * (S / 4) + threadIdx.x;
    #pragma unroll 4
    for (int it = 0; it < (S / 4) / 256; it++) {
        const size_t i = base + (size_t)it * 256;
        const float4 a = __ldcs(hr + i);
        const float4 b = __ldcs(hi + i);
        float4 o0, o1;
        o0.x = a.x * ckr - b.x * cki;  o1.x = fmaf(a.x, cki, b.x * ckr);
        o0.y = a.y * ckr - b.y * cki;  o1.y = fmaf(a.y, cki, b.y * ckr);
        o0.z = a.z * ckr - b.z * cki;  o1.z = fmaf(a.z, cki, b.z * ckr);
        o0.w = a.w * ckr - b.w * cki;  o1.w = fmaf(a.w, cki, b.w * ckr);
        __stcs(out + i, o0);
        __stcs(out + i + (size_t)W * (S / 4), o1);
    }
}

extern "C" void kernel_launch(void* const* d_in, const int* in_sizes, int n_in,
                              void* d_out, int out_size) {
    const float* holo_re = (const float*)d_in[0];
    const float* holo_im = (const float*)d_in[1];
    const float* cue_re  = (const float*)d_in[2];
    const float* cue_im  = (const float*)d_in[3];
    const float* keys_re = (const float*)d_in[4];
    const float* keys_im = (const float*)d_in[5];
    float* out = (float*)d_out;

    k_mix<<<W, 256>>>((const float4*)holo_re, (const float4*)holo_im,
                      (const float4*)cue_re, (const float4*)cue_im);
    k_corr<<<NK, 256>>>((const float4*)keys_re, (const float4*)keys_im);
    k_soft_compact<<<1, NK>>>();
    k_out<<<W, 256>>>((const float4*)holo_re, (const float4*)holo_im,
                      keys_re, keys_im, (float4*)out);
}

// round 4
// speedup vs baseline: 1.1462x; 1.0479x over previous
#include <cuda_runtime.h>

#define W 4096
#define S 4096
#define NK 1024
#define SHARP 10.0f
#define ATT_EPS 1e-8f   // keys below this attention contribute <1e-5 rel -> drop

// ---- scratch (device globals; no allocations allowed) ----
__device__ __align__(16) float g_mix_re[W];
__device__ __align__(16) float g_mix_im[W];
__device__ float g_corr[NK];
__device__ int   g_cidx[NK];   // compacted key indices with att > ATT_EPS
__device__ float g_catt[NK];   // their attention weights
__device__ int   g_cnt;        // number of compacted entries

// ---------------------------------------------------------------------------
// Stage 1: noisy_mix[w] = sum_s holo[w,s] * conj(cue[w,s])
//   re = hr*cr + hi*ci ; im = hi*cr - hr*ci
// holo: DEFAULT caching (evict-normal) -> its tail stays L2-resident for k_out.
// cue:  __ldcs (evict-first), it is never read again.
// ---------------------------------------------------------------------------
__global__ void __launch_bounds__(256) k_mix(
        const float4* __restrict__ hr, const float4* __restrict__ hi,
        const float4* __restrict__ cr, const float4* __restrict__ ci) {
    const int w = blockIdx.x;
    const size_t base = (size_t)w * (S / 4) + threadIdx.x;
    float are = 0.f, aim = 0.f;
    #pragma unroll 4
    for (int it = 0; it < (S / 4) / 256; it++) {
        const size_t idx = base + (size_t)it * 256;
        float4 a = hr[idx];
        float4 b = hi[idx];
        float4 c = __ldcs(cr + idx);
        float4 d = __ldcs(ci + idx);
        are += a.x * c.x + b.x * d.x;  aim += b.x * c.x - a.x * d.x;
        are += a.y * c.y + b.y * d.y;  aim += b.y * c.y - a.y * d.y;
        are += a.z * c.z + b.z * d.z;  aim += b.z * c.z - a.z * d.z;
        are += a.w * c.w + b.w * d.w;  aim += b.w * c.w - a.w * d.w;
    }
    __shared__ float s1[8], s2[8];
    #pragma unroll
    for (int o = 16; o > 0; o >>= 1) {
        are += __shfl_down_sync(0xffffffffu, are, o);
        aim += __shfl_down_sync(0xffffffffu, aim, o);
    }
    const int lane = threadIdx.x & 31, wid = threadIdx.x >> 5;
    if (lane == 0) { s1[wid] = are; s2[wid] = aim; }
    __syncthreads();
    if (wid == 0) {
        are = (lane < 8) ? s1[lane] : 0.f;
        aim = (lane < 8) ? s2[lane] : 0.f;
        #pragma unroll
        for (int o = 4; o > 0; o >>= 1) {
            are += __shfl_down_sync(0xffffffffu, are, o);
            aim += __shfl_down_sync(0xffffffffu, aim, o);
        }
        if (lane == 0) { g_mix_re[w] = are; g_mix_im[w] = aim; }
    }
}

// ---------------------------------------------------------------------------
// Stage 2: corr[n] = | keys[n,:] . mix |   (plain complex dot, NO conjugate)
// keys via __ldcs so the 32MB stream doesn't evict the resident holo tail.
// ---------------------------------------------------------------------------
__global__ void __launch_bounds__(256) k_corr(
        const float4* __restrict__ kr, const float4* __restrict__ ki) {
    const int n = blockIdx.x;
    const size_t base = (size_t)n * (W / 4) + threadIdx.x;
    const float4* __restrict__ mr = (const float4*)g_mix_re;
    const float4* __restrict__ mi = (const float4*)g_mix_im;
    float ar = 0.f, ai = 0.f;
    #pragma unroll 4
    for (int it = 0; it < (W / 4) / 256; it++) {
        const int i = threadIdx.x + it * 256;
        float4 a = __ldcs(kr + base + (size_t)it * 256);
        float4 b = __ldcs(ki + base + (size_t)it * 256);
        float4 c = mr[i];
        float4 d = mi[i];
        ar += a.x * c.x - b.x * d.x;  ai += a.x * d.x + b.x * c.x;
        ar += a.y * c.y - b.y * d.y;  ai += a.y * d.y + b.y * c.y;
        ar += a.z * c.z - b.z * d.z;  ai += a.z * d.z + b.z * c.z;
        ar += a.w * c.w - b.w * d.w;  ai += a.w * d.w + b.w * c.w;
    }
    __shared__ float s1[8], s2[8];
    #pragma unroll
    for (int o = 16; o > 0; o >>= 1) {
        ar += __shfl_down_sync(0xffffffffu, ar, o);
        ai += __shfl_down_sync(0xffffffffu, ai, o);
    }
    const int lane = threadIdx.x & 31, wid = threadIdx.x >> 5;
    if (lane == 0) { s1[wid] = ar; s2[wid] = ai; }
    __syncthreads();
    if (wid == 0) {
        ar = (lane < 8) ? s1[lane] : 0.f;
        ai = (lane < 8) ? s2[lane] : 0.f;
        #pragma unroll
        for (int o = 4; o > 0; o >>= 1) {
            ar += __shfl_down_sync(0xffffffffu, ar, o);
            ai += __shfl_down_sync(0xffffffffu, ai, o);
        }
        if (lane == 0) g_corr[n] = sqrtf(ar * ar + ai * ai);
    }
}

// ---------------------------------------------------------------------------
// Stage 3: softmax(corr*SHARP) + deterministic compaction of significant keys.
// ---------------------------------------------------------------------------
__global__ void k_soft_compact() {
    __shared__ float sm[NK];
    __shared__ int   sp[NK];
    const int t = threadIdx.x;
    const float x = g_corr[t] * SHARP;
    sm[t] = x;
    __syncthreads();
    #pragma unroll
    for (int o = NK / 2; o > 0; o >>= 1) {
        if (t < o) sm[t] = fmaxf(sm[t], sm[t + o]);
        __syncthreads();
    }
    const float mx = sm[0];
    __syncthreads();
    const float e = expf(x - mx);
    sm[t] = e;
    __syncthreads();
    #pragma unroll
    for (int o = NK / 2; o > 0; o >>= 1) {
        if (t < o) sm[t] += sm[t + o];
        __syncthreads();
    }
    const float att = e / sm[0];
    __syncthreads();
    // inclusive prefix sum of significance flags (deterministic index order)
    const int flag = (att > ATT_EPS) ? 1 : 0;
    sp[t] = flag;
    __syncthreads();
    #pragma unroll
    for (int o = 1; o < NK; o <<= 1) {
        int v = (t >= o) ? sp[t - o] : 0;
        __syncthreads();
        sp[t] += v;
        __syncthreads();
    }
    if (flag) {
        const int pos = sp[t] - 1;
        g_cidx[pos] = t;
        g_catt[pos] = att;
    }
    if (t == NK - 1) g_cnt = sp[t];
}

// ---------------------------------------------------------------------------
// Stage 4+5 fused: per row w, clean_key[w] = sum_j catt[j]*keys[cidx[j], w],
// then out[0] = hr*ckr - hi*cki ; out[1] = hr*cki + hi*ckr.
// Rows processed in REVERSE order so the first rows read are the holo rows
// most recently cached by k_mix (L2 reuse). holo reads are last-use -> __ldcs.
// ---------------------------------------------------------------------------
__global__ void __launch_bounds__(256) k_out(
        const float4* __restrict__ hr, const float4* __restrict__ hi,
        const float* __restrict__ kr, const float* __restrict__ ki,
        float4* __restrict__ out) {
    const int w = (W - 1) - blockIdx.x;   // reverse row order
    const int cnt = g_cnt;
    float ckr = 0.f, cki = 0.f;
    for (int j = 0; j < cnt; j++) {
        const float a = g_catt[j];
        const size_t off = (size_t)g_cidx[j] * W + w;
        ckr = fmaf(a, __ldg(kr + off), ckr);
        cki = fmaf(a, __ldg(ki + off), cki);
    }
    const size_t base = (size_t)w * (S / 4) + threadIdx.x;
    #pragma unroll 4
    for (int it = 0; it < (S / 4) / 256; it++) {
        const size_t i = base + (size_t)it * 256;
        const float4 a = __ldcs(hr + i);
        const float4 b = __ldcs(hi + i);
        float4 o0, o1;
        o0.x = a.x * ckr - b.x * cki;  o1.x = fmaf(a.x, cki, b.x * ckr);
        o0.y = a.y * ckr - b.y * cki;  o1.y = fmaf(a.y, cki, b.y * ckr);
        o0.z = a.z * ckr - b.z * cki;  o1.z = fmaf(a.z, cki, b.z * ckr);
        o0.w = a.w * ckr - b.w * cki;  o1.w = fmaf(a.w, cki, b.w * ckr);
        __stcs(out + i, o0);
        __stcs(out + i + (size_t)W * (S / 4), o1);
    }
}

extern "C" void kernel_launch(void* const* d_in, const int* in_sizes, int n_in,
                              void* d_out, int out_size) {
    const float* holo_re = (const float*)d_in[0];
    const float* holo_im = (const float*)d_in[1];
    const float* cue_re  = (const float*)d_in[2];
    const float* cue_im  = (const float*)d_in[3];
    const float* keys_re = (const float*)d_in[4];
    const float* keys_im = (const float*)d_in[5];
    float* out = (float*)d_out;

    k_mix<<<W, 256>>>((const float4*)holo_re, (const float4*)holo_im,
                      (const float4*)cue_re, (const float4*)cue_im);
    k_corr<<<NK, 256>>>((const float4*)keys_re, (const float4*)keys_im);
    k_soft_compact<<<1, NK>>>();
    k_out<<<W, 256>>>((const float4*)holo_re, (const float4*)holo_im,
                      keys_re, keys_im, (float4*)out);
}

// round 5
// speedup vs baseline: 1.1682x; 1.0192x over previous
#include <cuda_runtime.h>

#define W 4096
#define S 4096
#define NK 1024
#define SHARP 10.0f
#define ATT_EPS 1e-8f     // keys below this attention contribute <1e-5 rel -> drop
#define KEEP_ROWS 3072    // last 3072 holo rows (96MB) kept L2-resident for k_out

// ---- scratch (device globals; no allocations allowed) ----
__device__ __align__(16) float g_mix_re[W];
__device__ __align__(16) float g_mix_im[W];
__device__ float g_corr[NK];
__device__ int   g_cidx[NK];   // compacted key indices with att > ATT_EPS
__device__ float g_catt[NK];   // their attention weights
__device__ int   g_cnt;        // number of compacted entries

// ---------------------------------------------------------------------------
// Stage 1: noisy_mix[w] = sum_s holo[w,s] * conj(cue[w,s])
//   re = hr*cr + hi*ci ; im = hi*cr - hr*ci
// holo rows >= W-KEEP_ROWS: default (evict-normal) -> stay L2-resident, no
// self-eviction since 96MB < L2. Other holo rows + all cue: __ldcs.
// ---------------------------------------------------------------------------
__global__ void __launch_bounds__(256) k_mix(
        const float4* __restrict__ hr, const float4* __restrict__ hi,
        const float4* __restrict__ cr, const float4* __restrict__ ci) {
    const int w = blockIdx.x;
    const size_t base = (size_t)w * (S / 4) + threadIdx.x;
    float are = 0.f, aim = 0.f;
    if (w >= W - KEEP_ROWS) {
        #pragma unroll 4
        for (int it = 0; it < (S / 4) / 256; it++) {
            const size_t idx = base + (size_t)it * 256;
            float4 a = hr[idx];
            float4 b = hi[idx];
            float4 c = __ldcs(cr + idx);
            float4 d = __ldcs(ci + idx);
            are += a.x * c.x + b.x * d.x;  aim += b.x * c.x - a.x * d.x;
            are += a.y * c.y + b.y * d.y;  aim += b.y * c.y - a.y * d.y;
            are += a.z * c.z + b.z * d.z;  aim += b.z * c.z - a.z * d.z;
            are += a.w * c.w + b.w * d.w;  aim += b.w * c.w - a.w * d.w;
        }
    } else {
        #pragma unroll 4
        for (int it = 0; it < (S / 4) / 256; it++) {
            const size_t idx = base + (size_t)it * 256;
            float4 a = __ldcs(hr + idx);
            float4 b = __ldcs(hi + idx);
            float4 c = __ldcs(cr + idx);
            float4 d = __ldcs(ci + idx);
            are += a.x * c.x + b.x * d.x;  aim += b.x * c.x - a.x * d.x;
            are += a.y * c.y + b.y * d.y;  aim += b.y * c.y - a.y * d.y;
            are += a.z * c.z + b.z * d.z;  aim += b.z * c.z - a.z * d.z;
            are += a.w * c.w + b.w * d.w;  aim += b.w * c.w - a.w * d.w;
        }
    }
    __shared__ float s1[8], s2[8];
    #pragma unroll
    for (int o = 16; o > 0; o >>= 1) {
        are += __shfl_down_sync(0xffffffffu, are, o);
        aim += __shfl_down_sync(0xffffffffu, aim, o);
    }
    const int lane = threadIdx.x & 31, wid = threadIdx.x >> 5;
    if (lane == 0) { s1[wid] = are; s2[wid] = aim; }
    __syncthreads();
    if (wid == 0) {
        are = (lane < 8) ? s1[lane] : 0.f;
        aim = (lane < 8) ? s2[lane] : 0.f;
        #pragma unroll
        for (int o = 4; o > 0; o >>= 1) {
            are += __shfl_down_sync(0xffffffffu, are, o);
            aim += __shfl_down_sync(0xffffffffu, aim, o);
        }
        if (lane == 0) { g_mix_re[w] = are; g_mix_im[w] = aim; }
    }
}

// ---------------------------------------------------------------------------
// Stage 2: corr[n] = | keys[n,:] . mix |   (plain complex dot, NO conjugate)
// keys via __ldcs so the 32MB stream doesn't evict the resident holo set.
// ---------------------------------------------------------------------------
__global__ void __launch_bounds__(256) k_corr(
        const float4* __restrict__ kr, const float4* __restrict__ ki) {
    const int n = blockIdx.x;
    const size_t base = (size_t)n * (W / 4) + threadIdx.x;
    const float4* __restrict__ mr = (const float4*)g_mix_re;
    const float4* __restrict__ mi = (const float4*)g_mix_im;
    float ar = 0.f, ai = 0.f;
    #pragma unroll 4
    for (int it = 0; it < (W / 4) / 256; it++) {
        const int i = threadIdx.x + it * 256;
        float4 a = __ldcs(kr + base + (size_t)it * 256);
        float4 b = __ldcs(ki + base + (size_t)it * 256);
        float4 c = mr[i];
        float4 d = mi[i];
        ar += a.x * c.x - b.x * d.x;  ai += a.x * d.x + b.x * c.x;
        ar += a.y * c.y - b.y * d.y;  ai += a.y * d.y + b.y * c.y;
        ar += a.z * c.z - b.z * d.z;  ai += a.z * d.z + b.z * c.z;
        ar += a.w * c.w - b.w * d.w;  ai += a.w * d.w + b.w * c.w;
    }
    __shared__ float s1[8], s2[8];
    #pragma unroll
    for (int o = 16; o > 0; o >>= 1) {
        ar += __shfl_down_sync(0xffffffffu, ar, o);
        ai += __shfl_down_sync(0xffffffffu, ai, o);
    }
    const int lane = threadIdx.x & 31, wid = threadIdx.x >> 5;
    if (lane == 0) { s1[wid] = ar; s2[wid] = ai; }
    __syncthreads();
    if (wid == 0) {
        ar = (lane < 8) ? s1[lane] : 0.f;
        ai = (lane < 8) ? s2[lane] : 0.f;
        #pragma unroll
        for (int o = 4; o > 0; o >>= 1) {
            ar += __shfl_down_sync(0xffffffffu, ar, o);
            ai += __shfl_down_sync(0xffffffffu, ai, o);
        }
        if (lane == 0) g_corr[n] = sqrtf(ar * ar + ai * ai);
    }
}

// ---------------------------------------------------------------------------
// Stage 3: softmax(corr*SHARP) + deterministic compaction, warp-shuffle based.
// 1024 threads = 32 warps. 4 __syncthreads total.
// ---------------------------------------------------------------------------
__global__ void k_soft_compact() {
    __shared__ float swarp[32];
    __shared__ int   scnt[32];
    __shared__ float s_mx, s_sum;
    const int t = threadIdx.x;
    const int lane = t & 31, wid = t >> 5;
    const float x = g_corr[t] * SHARP;

    // block max
    float m = x;
    #pragma unroll
    for (int o = 16; o > 0; o >>= 1) m = fmaxf(m, __shfl_xor_sync(0xffffffffu, m, o));
    if (lane == 0) swarp[wid] = m;
    __syncthreads();
    if (t < 32) {
        m = swarp[t];
        #pragma unroll
        for (int o = 16; o > 0; o >>= 1) m = fmaxf(m, __shfl_xor_sync(0xffffffffu, m, o));
        if (t == 0) s_mx = m;
    }
    __syncthreads();
    const float e = expf(x - s_mx);

    // block sum
    float sm = e;
    #pragma unroll
    for (int o = 16; o > 0; o >>= 1) sm += __shfl_xor_sync(0xffffffffu, sm, o);
    if (lane == 0) swarp[wid] = sm;
    __syncthreads();
    if (t < 32) {
        sm = swarp[t];
        #pragma unroll
        for (int o = 16; o > 0; o >>= 1) sm += __shfl_xor_sync(0xffffffffu, sm, o);
        if (t == 0) s_sum = sm;
    }
    __syncthreads();
    const float att = e / s_sum;

    // deterministic compaction: ballot within warp + exclusive scan of warp counts
    const bool flag = (att > ATT_EPS);
    const unsigned bal = __ballot_sync(0xffffffffu, flag);
    const int in_warp = __popc(bal & ((1u << lane) - 1u));
    if (lane == 0) scnt[wid] = __popc(bal);
    __syncthreads();
    if (t < 32) {
        int v = scnt[t];
        int excl = 0;
        #pragma unroll
        for (int o = 1; o < 32; o <<= 1) {
            int u = __shfl_up_sync(0xffffffffu, v, o);
            if (t >= o) v += u;
        }
        excl = v - scnt[t];
        scnt[t] = excl;
        if (t == 31) g_cnt = excl + __popc(bal);  // warp 0's bal? no -- fix below
    }
    __syncthreads();
    if (flag) {
        const int pos = scnt[wid] + in_warp;
        g_cidx[pos] = t;
        g_catt[pos] = att;
    }
    // total count: last warp's exclusive offset + its own count
    if (t == NK - 32) {  // lane 0 of last warp
        g_cnt = scnt[31] + __popc(bal);
    }
}

// ---------------------------------------------------------------------------
// Stage 4+5 fused: per row w, clean_key[w] = sum_j catt[j]*keys[cidx[j], w],
// then out[0] = hr*ckr - hi*cki ; out[1] = hr*cki + hi*ckr.
// Reverse row order: first rows read are the L2-resident holo rows.
// ---------------------------------------------------------------------------
__global__ void __launch_bounds__(256) k_out(
        const float4* __restrict__ hr, const float4* __restrict__ hi,
        const float* __restrict__ kr, const float* __restrict__ ki,
        float4* __restrict__ out) {
    const int w = (W - 1) - blockIdx.x;   // reverse row order
    const int cnt = g_cnt;
    float ckr = 0.f, cki = 0.f;
    for (int j = 0; j < cnt; j++) {
        const float a = g_catt[j];
        const size_t off = (size_t)g_cidx[j] * W + w;
        ckr = fmaf(a, __ldg(kr + off), ckr);
        cki = fmaf(a, __ldg(ki + off), cki);
    }
    const size_t base = (size_t)w * (S / 4) + threadIdx.x;
    #pragma unroll 4
    for (int it = 0; it < (S / 4) / 256; it++) {
        const size_t i = base + (size_t)it * 256;
        const float4 a = __ldcs(hr + i);
        const float4 b = __ldcs(hi + i);
        float4 o0, o1;
        o0.x = a.x * ckr - b.x * cki;  o1.x = fmaf(a.x, cki, b.x * ckr);
        o0.y = a.y * ckr - b.y * cki;  o1.y = fmaf(a.y, cki, b.y * ckr);
        o0.z = a.z * ckr - b.z * cki;  o1.z = fmaf(a.z, cki, b.z * ckr);
        o0.w = a.w * ckr - b.w * cki;  o1.w = fmaf(a.w, cki, b.w * ckr);
        __stcs(out + i, o0);
        __stcs(out + i + (size_t)W * (S / 4), o1);
    }
}

extern "C" void kernel_launch(void* const* d_in, const int* in_sizes, int n_in,
                              void* d_out, int out_size) {
    const float* holo_re = (const float*)d_in[0];
    const float* holo_im = (const float*)d_in[1];
    const float* cue_re  = (const float*)d_in[2];
    const float* cue_im  = (const float*)d_in[3];
    const float* keys_re = (const float*)d_in[4];
    const float* keys_im = (const float*)d_in[5];
    float* out = (float*)d_out;

    k_mix<<<W, 256>>>((const float4*)holo_re, (const float4*)holo_im,
                      (const float4*)cue_re, (const float4*)cue_im);
    k_corr<<<NK, 256>>>((const float4*)keys_re, (const float4*)keys_im);
    k_soft_compact<<<1, NK>>>();
    k_out<<<W, 256>>>((const float4*)holo_re, (const float4*)holo_im,
                      keys_re, keys_im, (float4*)out);
}